// round 10
// baseline (speedup 1.0000x reference)
#include <cuda_runtime.h>
#include <cuda_bf16.h>
#include <cuda_fp16.h>
#include <math.h>
#include <stdint.h>

#define N     8192
#define D     128
#define TWON  16384
#define NTILE 128
#define NPAIR 8256             // NTILE*(NTILE+1)/2
#define CHUNK 8

#define DIAG_EXP2  7.38905609893065f
#define SQRT_SCALE 1.6986436f  // sqrt(2/ln2): acc = log2(exp arg)

// -------- persistent device scratch --------
__device__ __nv_bfloat16 g_Hb[TWON * D];
__device__ float g_pos[N];
__device__ float g_rowsum[TWON];
__device__ int   g_ctr;

// ============================================================
// helpers
// ============================================================
__device__ __forceinline__ uint32_t smem_u32(const void* p) {
    uint32_t a;
    asm("{ .reg .u64 t; cvta.to.shared.u64 t, %1; cvt.u32.u64 %0, t; }" : "=r"(a) : "l"(p));
    return a;
}
__device__ __forceinline__ void cp_async16(uint32_t saddr, const void* gaddr) {
    asm volatile("cp.async.cg.shared.global [%0], [%1], 16;" :: "r"(saddr), "l"(gaddr) : "memory");
}
#define CP_COMMIT() asm volatile("cp.async.commit_group;" ::: "memory")
#define CP_WAIT1()  asm volatile("cp.async.wait_group 1;" ::: "memory")

__device__ __forceinline__ void ldmatrix_x4(uint32_t& r0, uint32_t& r1, uint32_t& r2,
                                            uint32_t& r3, uint32_t addr) {
    asm volatile("ldmatrix.sync.aligned.m8n8.x4.shared.b16 {%0,%1,%2,%3}, [%4];"
                 : "=r"(r0), "=r"(r1), "=r"(r2), "=r"(r3) : "r"(addr));
}
__device__ __forceinline__ void mma_bf16(float* c, const uint32_t* a, uint32_t b0, uint32_t b1) {
    asm volatile("mma.sync.aligned.m16n8k16.row.col.f32.bf16.bf16.f32 "
                 "{%0,%1,%2,%3}, {%4,%5,%6,%7}, {%8,%9}, {%0,%1,%2,%3};"
                 : "+f"(c[0]), "+f"(c[1]), "+f"(c[2]), "+f"(c[3])
                 : "r"(a[0]), "r"(a[1]), "r"(a[2]), "r"(a[3]), "r"(b0), "r"(b1));
}
__device__ __forceinline__ uint32_t f16x2_pack(float lo, float hi) {
    uint32_t r;  // cvt.rn.f16x2.f32 d,a,b : high=a, low=b
    asm("cvt.rn.f16x2.f32 %0, %1, %2;" : "=r"(r) : "f"(hi), "f"(lo));
    return r;
}
__device__ __forceinline__ uint32_t ex2_f16x2(uint32_t x) {
    uint32_t y;
    asm("ex2.approx.f16x2 %0, %1;" : "=r"(y) : "r"(x));
    return y;
}
__device__ __forceinline__ uint32_t hadd2(uint32_t a, uint32_t b) {
    uint32_t r;
    asm("add.rn.f16x2 %0, %1, %2;" : "=r"(r) : "r"(a), "r"(b));
    return r;
}
// t in [0, NPAIR) -> (I,J), I<=J, row-major over upper triangle
__device__ __forceinline__ void decode_pair(int t, int& I, int& J) {
    int r = NPAIR - t;
    float nf = (sqrtf(8.0f * (float)r + 1.0f) - 1.0f) * 0.5f;
    int n = (int)ceilf(nf);
    while (n * (n + 1) / 2 < r) n++;
    while (n >= 1 && (n - 1) * n / 2 >= r) n--;
    I = NTILE - n;
    int S = NPAIR - n * (n + 1) / 2;
    J = I + (t - S);
}

// ============================================================
// Kernel A: normalize + pre-scale to bf16; zero rowsum/ctr
// ============================================================
__global__ void nt_norm_kernel(const float* __restrict__ h1,
                               const float* __restrict__ h2) {
    int gid = blockIdx.x * blockDim.x + threadIdx.x;
    if (gid < TWON) g_rowsum[gid] = 0.0f;
    if (gid == 0)   g_ctr = 0;

    int warp = gid >> 5;
    int lane = threadIdx.x & 31;
    if (warp >= N) return;

    float4 a = ((const float4*)(h1 + (size_t)warp * D))[lane];
    float4 b = ((const float4*)(h2 + (size_t)warp * D))[lane];

    float sa = a.x*a.x + a.y*a.y + a.z*a.z + a.w*a.w;
    float sb = b.x*b.x + b.y*b.y + b.z*b.z + b.w*b.w;
    float sd = a.x*b.x + a.y*b.y + a.z*b.z + a.w*b.w;
    #pragma unroll
    for (int o = 16; o; o >>= 1) {
        sa += __shfl_xor_sync(0xffffffffu, sa, o);
        sb += __shfl_xor_sync(0xffffffffu, sb, o);
        sd += __shfl_xor_sync(0xffffffffu, sd, o);
    }
    float ra = 1.0f / fmaxf(sqrtf(sa), 1e-12f);
    float rb = 1.0f / fmaxf(sqrtf(sb), 1e-12f);
    if (lane == 0) g_pos[warp] = sd * ra * rb;

    float fa = ra * SQRT_SCALE, fb = rb * SQRT_SCALE;
    union { __nv_bfloat162 b2[2]; uint2 u; } pa, pb;
    pa.b2[0] = __floats2bfloat162_rn(a.x*fa, a.y*fa);
    pa.b2[1] = __floats2bfloat162_rn(a.z*fa, a.w*fa);
    pb.b2[0] = __floats2bfloat162_rn(b.x*fb, b.y*fb);
    pb.b2[1] = __floats2bfloat162_rn(b.z*fb, b.w*fb);
    ((uint2*)(g_Hb + (size_t)warp * D))[lane]       = pa.u;
    ((uint2*)(g_Hb + (size_t)(warp + N) * D))[lane] = pb.u;
}

// ============================================================
// Kernel B: symmetric persistent GEMM, chunked I-locality,
//   triple-buffered tiles, STRIP-PIPELINED epilogue
//   (strip s epilogue overlaps strip s+1 MMA on tensor pipe).
// ============================================================
#define PADROW    136
#define ROWB      (PADROW * 2)           // 272B
#define T_BYTES   (128 * ROWB)           // 34816
#define BUF_BYTES (2 * T_BYTES)
#define SMEM_SZ   (3 * BUF_BYTES)        // 208896
#define NT        256

__device__ __forceinline__ void cp_tileA(uint32_t buf, int I, int tid) {
    const __nv_bfloat16* src = g_Hb + (size_t)I * 128 * D;
    #pragma unroll
    for (int c = tid; c < 2048; c += NT) {
        int r = c >> 4, kc = c & 15;
        cp_async16(buf + r * ROWB + kc * 16, src + (size_t)r * D + kc * 8);
    }
}
__device__ __forceinline__ void cp_tileB(uint32_t buf, int J, int tid) {
    const __nv_bfloat16* src = g_Hb + (size_t)J * 128 * D;
    #pragma unroll
    for (int c = tid; c < 2048; c += NT) {
        int r = c >> 4, kc = c & 15;
        cp_async16(buf + T_BYTES + r * ROWB + kc * 16, src + (size_t)r * D + kc * 8);
    }
}

// issue LDSM + 32 MMAs for one 16-col n-strip into acc (async on tensor pipe)
__device__ __forceinline__ void strip_mma(float acc[2][2][4], uint32_t bbase, int pr,
                                          const uint32_t afrag[8][2][4]) {
    #pragma unroll
    for (int ma = 0; ma < 2; ++ma)
        #pragma unroll
        for (int nl = 0; nl < 2; ++nl)
            #pragma unroll
            for (int q = 0; q < 4; ++q) acc[ma][nl][q] = 0.f;

    uint32_t bq[2][4];
    ldmatrix_x4(bq[0][0], bq[0][1], bq[0][2], bq[0][3], bbase + pr * 16 * ROWB);
    #pragma unroll
    for (int kst = 0; kst < 8; ++kst) {
        int cb = kst & 1, nb = cb ^ 1;
        if (kst < 7)
            ldmatrix_x4(bq[nb][0], bq[nb][1], bq[nb][2], bq[nb][3],
                        bbase + pr * 16 * ROWB + (kst + 1) * 32);
        mma_bf16(acc[0][0], afrag[kst][0], bq[cb][0], bq[cb][2]);
        mma_bf16(acc[0][1], afrag[kst][0], bq[cb][1], bq[cb][3]);
        mma_bf16(acc[1][0], afrag[kst][1], bq[cb][0], bq[cb][2]);
        mma_bf16(acc[1][1], afrag[kst][1], bq[cb][1], bq[cb][3]);
    }
}

__global__ void __launch_bounds__(NT, 1) nt_gemm_sym() {
    extern __shared__ char smem[];
    __shared__ int s_c;
    uint32_t sb = smem_u32(smem);
    const int tid    = threadIdx.x;
    const int lane   = tid & 31;
    const int wid    = tid >> 5;
    const int warp_m = wid & 3;
    const int warp_n = wid >> 2;

    // ---- first chunk ----
    if (tid == 0) s_c = atomicAdd(&g_ctr, 1);
    __syncthreads();
    int cpos = s_c * CHUNK;
    int cend = cpos + CHUNK;
    if (cpos >= NPAIR) { cpos = NPAIR; cend = NPAIR; }

    int curT = (cpos < cend) ? cpos++ : NPAIR;
    int curI = 0, curJ = 0;
    if (curT < NPAIR) decode_pair(curT, curI, curJ);
    if (curT < NPAIR) { cp_tileA(sb, curI, tid); cp_tileB(sb, curJ, tid); }
    CP_COMMIT();

    int nxtT = (cpos < cend) ? cpos++ : NPAIR;
    int nxtI = 0, nxtJ = 0;
    if (nxtT < NPAIR) decode_pair(nxtT, nxtI, nxtJ);
    if (nxtT < NPAIR) {
        if (nxtI != curI) cp_tileA(sb + BUF_BYTES, nxtI, tid);
        cp_tileB(sb + BUF_BYTES, nxtJ, tid);
    }
    CP_COMMIT();

    int p = 0, prevI = -1;
    uint32_t afrag[8][2][4];
    float rs[4] = {0.f, 0.f, 0.f, 0.f};

    while (curT < NPAIR) {
        // ---- schedule next-next tile ----
        bool need = (cpos >= cend);
        if (need && tid == 0) s_c = atomicAdd(&g_ctr, 1);
        CP_WAIT1();
        __syncthreads();
        if (need) {
            cpos = s_c * CHUNK;
            if (cpos > NPAIR) cpos = NPAIR;
            cend = cpos + CHUNK;
            if (cend > NPAIR) cend = NPAIR;
        }
        int t2 = (cpos < cend) ? cpos++ : NPAIR;
        int I2 = 0, J2 = 0;
        if (t2 < NPAIR) {
            decode_pair(t2, I2, J2);
            int pb = p + 2; if (pb >= 3) pb -= 3;
            uint32_t pbuf = sb + pb * BUF_BYTES;
            if (I2 != nxtI) cp_tileA(pbuf, I2, tid);
            cp_tileB(pbuf, J2, tid);
        }
        CP_COMMIT();

        uint32_t abuf = sb + p * BUF_BYTES;
        uint32_t bbuf = abuf + T_BYTES;

        // ---- I changed: flush deferred row sums, reload A fragments ----
        if (curI != prevI) {
            if (prevI >= 0) {
                #pragma unroll
                for (int i = 0; i < 4; ++i) {
                    rs[i] += __shfl_xor_sync(0xffffffffu, rs[i], 1);
                    rs[i] += __shfl_xor_sync(0xffffffffu, rs[i], 2);
                }
                if ((lane & 3) == 0) {
                    int r8 = lane >> 2;
                    #pragma unroll
                    for (int i = 0; i < 4; ++i)
                        atomicAdd(&g_rowsum[prevI * 128 + warp_m * 32 + i * 8 + r8], rs[i]);
                }
                rs[0] = rs[1] = rs[2] = rs[3] = 0.f;
            }
            uint32_t abase = abuf + (warp_m * 32 + (lane & 15)) * ROWB + (lane >> 4) * 16;
            #pragma unroll
            for (int kst = 0; kst < 8; ++kst)
                #pragma unroll
                for (int ma = 0; ma < 2; ++ma)
                    ldmatrix_x4(afrag[kst][ma][0], afrag[kst][ma][1],
                                afrag[kst][ma][2], afrag[kst][ma][3],
                                abase + ma * 16 * ROWB + kst * 32);
        }
        prevI = curI;

        const bool diag = (curI == curJ);
        uint32_t colacc[8];
        #pragma unroll
        for (int na = 0; na < 8; ++na) colacc[na] = 0;
        uint32_t rlo[2] = {0, 0}, rhi[2] = {0, 0};

        uint32_t bbase = bbuf + (warp_n * 64 + (lane & 15)) * ROWB + (lane >> 4) * 16;

        // ---- strip-pipelined compute: epilogue(s) overlaps MMA(s+1) ----
        float acc[2][2][2][4];   // [pipeline buf][ma][nl][q]
        strip_mma(acc[0], bbase, 0, afrag);
        #pragma unroll
        for (int pr = 0; pr < 4; ++pr) {
            if (pr < 3) strip_mma(acc[(pr + 1) & 1], bbase, pr + 1, afrag);
            float (*A)[2][4] = acc[pr & 1];
            #pragma unroll
            for (int ma = 0; ma < 2; ++ma)
                #pragma unroll
                for (int nl = 0; nl < 2; ++nl) {
                    uint32_t e01 = ex2_f16x2(f16x2_pack(A[ma][nl][0], A[ma][nl][1]));
                    uint32_t e23 = ex2_f16x2(f16x2_pack(A[ma][nl][2], A[ma][nl][3]));
                    rlo[ma] = hadd2(rlo[ma], e01);
                    rhi[ma] = hadd2(rhi[ma], e23);
                    colacc[pr * 2 + nl] = hadd2(colacc[pr * 2 + nl], hadd2(e01, e23));
                }
        }

        // fold tile row partials into persistent f32
        #pragma unroll
        for (int ma = 0; ma < 2; ++ma) {
            float2 glo = __half22float2(*(__half2*)&rlo[ma]);
            float2 ghi = __half22float2(*(__half2*)&rhi[ma]);
            rs[ma*2]     += glo.x + glo.y;
            rs[ma*2 + 1] += ghi.x + ghi.y;
        }

        // ---- colsum flush (per tile; symmetry) ----
        if (!diag) {
            #pragma unroll
            for (int na = 0; na < 8; ++na) {
                uint32_t v = colacc[na];
                v = hadd2(v, __shfl_xor_sync(0xffffffffu, v, 4));
                v = hadd2(v, __shfl_xor_sync(0xffffffffu, v, 8));
                v = hadd2(v, __shfl_xor_sync(0xffffffffu, v, 16));
                if (lane < 4) {
                    float2 cs = __half22float2(*(__half2*)&v);
                    int col = curJ * 128 + warp_n * 64 + na * 8 + lane * 2;
                    atomicAdd(&g_rowsum[col],     cs.x);
                    atomicAdd(&g_rowsum[col + 1], cs.y);
                }
            }
        }

        // ---- rotate ----
        curT = nxtT; curI = nxtI; curJ = nxtJ;
        nxtT = t2;   nxtI = I2;   nxtJ = J2;
        p = (p == 2) ? 0 : p + 1;
    }

    // ---- final deferred row flush ----
    if (prevI >= 0) {
        #pragma unroll
        for (int i = 0; i < 4; ++i) {
            rs[i] += __shfl_xor_sync(0xffffffffu, rs[i], 1);
            rs[i] += __shfl_xor_sync(0xffffffffu, rs[i], 2);
        }
        if ((lane & 3) == 0) {
            int r8 = lane >> 2;
            #pragma unroll
            for (int i = 0; i < 4; ++i)
                atomicAdd(&g_rowsum[prevI * 128 + warp_m * 32 + i * 8 + r8], rs[i]);
        }
    }
}

// ============================================================
// Kernel C: loss = mean( log(rowsum - exp(2)) - 2*pos )
// ============================================================
__global__ void nt_loss_kernel(float* __restrict__ out) {
    __shared__ double sred[32];
    const int tid  = threadIdx.x;   // 1024
    const int lane = tid & 31;
    const int wid  = tid >> 5;

    double s = 0.0;
    for (int i = tid; i < TWON; i += 1024) {
        float denom = g_rowsum[i] - DIAG_EXP2;
        float term  = logf(denom) - 2.0f * g_pos[i & (N - 1)];
        s += (double)term;
    }
    #pragma unroll
    for (int o = 16; o; o >>= 1) s += __shfl_xor_sync(0xffffffffu, s, o);
    if (lane == 0) sred[wid] = s;
    __syncthreads();
    if (wid == 0) {
        double tt = sred[lane];
        #pragma unroll
        for (int o = 16; o; o >>= 1) tt += __shfl_xor_sync(0xffffffffu, tt, o);
        if (lane == 0) out[0] = (float)(tt / (double)TWON);
    }
}

// ============================================================
extern "C" void kernel_launch(void* const* d_in, const int* in_sizes, int n_in,
                              void* d_out, int out_size) {
    const float* h1 = (const float*)d_in[0];
    const float* h2 = (const float*)d_in[1];
    float* out = (float*)d_out;

    nt_norm_kernel<<<1024, 256>>>(h1, h2);

    cudaFuncSetAttribute(nt_gemm_sym,
                         cudaFuncAttributeMaxDynamicSharedMemorySize, SMEM_SZ);
    nt_gemm_sym<<<148, NT, SMEM_SZ>>>();

    nt_loss_kernel<<<1, 1024>>>(out);
}

// round 11
// speedup vs baseline: 1.2435x; 1.2435x over previous
#include <cuda_runtime.h>
#include <cuda_bf16.h>
#include <cuda_fp16.h>
#include <math.h>
#include <stdint.h>

#define N     8192
#define D     128
#define TWON  16384
#define NTILE 128
#define NPAIR 8256             // NTILE*(NTILE+1)/2
#define CHUNK 4

#define DIAG_EXP2  7.38905609893065f
#define SQRT_SCALE 1.6986436f  // sqrt(2/ln2): acc = log2(exp arg)

// -------- persistent device scratch --------
__device__ __nv_bfloat16 g_Hb[TWON * D];
__device__ float g_pos[N];
__device__ float g_rowsum[TWON];
__device__ int   g_ctr;

// ============================================================
// helpers
// ============================================================
__device__ __forceinline__ uint32_t smem_u32(const void* p) {
    uint32_t a;
    asm("{ .reg .u64 t; cvta.to.shared.u64 t, %1; cvt.u32.u64 %0, t; }" : "=r"(a) : "l"(p));
    return a;
}
__device__ __forceinline__ void cp_async16(uint32_t saddr, const void* gaddr) {
    asm volatile("cp.async.cg.shared.global [%0], [%1], 16;" :: "r"(saddr), "l"(gaddr) : "memory");
}
#define CP_COMMIT() asm volatile("cp.async.commit_group;" ::: "memory")
#define CP_WAIT0()  asm volatile("cp.async.wait_group 0;" ::: "memory")

__device__ __forceinline__ void ldmatrix_x4(uint32_t& r0, uint32_t& r1, uint32_t& r2,
                                            uint32_t& r3, uint32_t addr) {
    asm volatile("ldmatrix.sync.aligned.m8n8.x4.shared.b16 {%0,%1,%2,%3}, [%4];"
                 : "=r"(r0), "=r"(r1), "=r"(r2), "=r"(r3) : "r"(addr));
}
__device__ __forceinline__ void mma_bf16(float* c, const uint32_t* a, uint32_t b0, uint32_t b1) {
    asm volatile("mma.sync.aligned.m16n8k16.row.col.f32.bf16.bf16.f32 "
                 "{%0,%1,%2,%3}, {%4,%5,%6,%7}, {%8,%9}, {%0,%1,%2,%3};"
                 : "+f"(c[0]), "+f"(c[1]), "+f"(c[2]), "+f"(c[3])
                 : "r"(a[0]), "r"(a[1]), "r"(a[2]), "r"(a[3]), "r"(b0), "r"(b1));
}
__device__ __forceinline__ uint32_t f16x2_pack(float lo, float hi) {
    uint32_t r;  // cvt.rn.f16x2.f32 d,a,b : high=a, low=b
    asm("cvt.rn.f16x2.f32 %0, %1, %2;" : "=r"(r) : "f"(hi), "f"(lo));
    return r;
}
__device__ __forceinline__ uint32_t ex2_f16x2(uint32_t x) {
    uint32_t y;
    asm("ex2.approx.f16x2 %0, %1;" : "=r"(y) : "r"(x));
    return y;
}
__device__ __forceinline__ uint32_t hadd2(uint32_t a, uint32_t b) {
    uint32_t r;
    asm("add.rn.f16x2 %0, %1, %2;" : "=r"(r) : "r"(a), "r"(b));
    return r;
}
// t in [0, NPAIR) -> (I,J), I<=J, row-major over upper triangle
__device__ __forceinline__ void decode_pair(int t, int& I, int& J) {
    int r = NPAIR - t;
    float nf = (sqrtf(8.0f * (float)r + 1.0f) - 1.0f) * 0.5f;
    int n = (int)ceilf(nf);
    while (n * (n + 1) / 2 < r) n++;
    while (n >= 1 && (n - 1) * n / 2 >= r) n--;
    I = NTILE - n;
    int S = NPAIR - n * (n + 1) / 2;
    J = I + (t - S);
}

// ============================================================
// Kernel A: normalize + pre-scale to bf16; zero rowsum/ctr
// ============================================================
__global__ void nt_norm_kernel(const float* __restrict__ h1,
                               const float* __restrict__ h2) {
    int gid = blockIdx.x * blockDim.x + threadIdx.x;
    if (gid < TWON) g_rowsum[gid] = 0.0f;
    if (gid == 0)   g_ctr = 0;

    int warp = gid >> 5;
    int lane = threadIdx.x & 31;
    if (warp >= N) return;

    float4 a = ((const float4*)(h1 + (size_t)warp * D))[lane];
    float4 b = ((const float4*)(h2 + (size_t)warp * D))[lane];

    float sa = a.x*a.x + a.y*a.y + a.z*a.z + a.w*a.w;
    float sb = b.x*b.x + b.y*b.y + b.z*b.z + b.w*b.w;
    float sd = a.x*b.x + a.y*b.y + a.z*b.z + a.w*b.w;
    #pragma unroll
    for (int o = 16; o; o >>= 1) {
        sa += __shfl_xor_sync(0xffffffffu, sa, o);
        sb += __shfl_xor_sync(0xffffffffu, sb, o);
        sd += __shfl_xor_sync(0xffffffffu, sd, o);
    }
    float ra = 1.0f / fmaxf(sqrtf(sa), 1e-12f);
    float rb = 1.0f / fmaxf(sqrtf(sb), 1e-12f);
    if (lane == 0) g_pos[warp] = sd * ra * rb;

    float fa = ra * SQRT_SCALE, fb = rb * SQRT_SCALE;
    union { __nv_bfloat162 b2[2]; uint2 u; } pa, pb;
    pa.b2[0] = __floats2bfloat162_rn(a.x*fa, a.y*fa);
    pa.b2[1] = __floats2bfloat162_rn(a.z*fa, a.w*fa);
    pb.b2[0] = __floats2bfloat162_rn(b.x*fb, b.y*fb);
    pb.b2[1] = __floats2bfloat162_rn(b.z*fb, b.w*fb);
    ((uint2*)(g_Hb + (size_t)warp * D))[lane]       = pa.u;
    ((uint2*)(g_Hb + (size_t)(warp + N) * D))[lane] = pb.u;
}

// ============================================================
// Kernel B: symmetric persistent GEMM — OCCUPANCY 2 version.
//   smem = A buf + 2 B bufs = 104448B -> 2 CTAs/SM, grid 296.
//   CTA-level bubbles (waits/syncs/flushes) hide under the
//   co-resident CTA's MMA stream.
// ============================================================
#define PADROW    136
#define ROWB      (PADROW * 2)           // 272B
#define T_BYTES   (128 * ROWB)           // 34816
#define A_OFF     0
#define B0_OFF    T_BYTES
#define B1_OFF    (2 * T_BYTES)
#define SMEM_SZ   (3 * T_BYTES)          // 104448
#define NT        256

__device__ __forceinline__ void cp_tile(uint32_t buf, int blk, int tid) {
    const __nv_bfloat16* src = g_Hb + (size_t)blk * 128 * D;
    #pragma unroll
    for (int c = tid; c < 2048; c += NT) {
        int r = c >> 4, kc = c & 15;
        cp_async16(buf + r * ROWB + kc * 16, src + (size_t)r * D + kc * 8);
    }
}

__global__ void __launch_bounds__(NT, 2) nt_gemm_sym() {
    extern __shared__ char smem[];
    __shared__ int s_c;
    uint32_t sb = smem_u32(smem);
    const int tid    = threadIdx.x;
    const int lane   = tid & 31;
    const int wid    = tid >> 5;
    const int warp_m = wid & 3;      // rows warp_m*32
    const int warp_n = wid >> 2;     // cols warp_n*64

    // ---- first chunk + first tile load ----
    if (tid == 0) s_c = atomicAdd(&g_ctr, 1);
    __syncthreads();
    int cpos = s_c * CHUNK;
    int cend = cpos + CHUNK;
    if (cpos >= NPAIR) { cpos = NPAIR; cend = NPAIR; }

    int curT = (cpos < cend) ? cpos++ : NPAIR;
    int curI = 0, curJ = 0;
    if (curT < NPAIR) {
        decode_pair(curT, curI, curJ);
        cp_tile(sb + A_OFF, curI, tid);
        cp_tile(sb + B0_OFF, curJ, tid);
    }
    CP_COMMIT();

    int p = 0, prevI = -1;
    uint32_t afrag[8][2][4];
    float rs[4] = {0.f, 0.f, 0.f, 0.f};

    while (curT < NPAIR) {
        // ---- acquire next index; wait cur data; one block sync ----
        bool need = (cpos >= cend);
        if (need && tid == 0) s_c = atomicAdd(&g_ctr, 1);
        CP_WAIT0();
        __syncthreads();
        if (need) {
            cpos = s_c * CHUNK;
            if (cpos > NPAIR) cpos = NPAIR;
            cend = cpos + CHUNK;
            if (cend > NPAIR) cend = NPAIR;
        }
        int nxtT = (cpos < cend) ? cpos++ : NPAIR;
        int nxtI = 0, nxtJ = 0;
        if (nxtT < NPAIR) decode_pair(nxtT, nxtI, nxtJ);

        // ---- I changed: flush deferred row sums, (re)load A fragments ----
        if (curI != prevI) {
            if (prevI >= 0) {
                #pragma unroll
                for (int i = 0; i < 4; ++i) {
                    rs[i] += __shfl_xor_sync(0xffffffffu, rs[i], 1);
                    rs[i] += __shfl_xor_sync(0xffffffffu, rs[i], 2);
                }
                if ((lane & 3) == 0) {
                    int r8 = lane >> 2;
                    #pragma unroll
                    for (int i = 0; i < 4; ++i)
                        atomicAdd(&g_rowsum[prevI * 128 + warp_m * 32 + i * 8 + r8], rs[i]);
                }
                rs[0] = rs[1] = rs[2] = rs[3] = 0.f;
            }
            uint32_t abase = sb + A_OFF + (warp_m * 32 + (lane & 15)) * ROWB + (lane >> 4) * 16;
            #pragma unroll
            for (int kst = 0; kst < 8; ++kst)
                #pragma unroll
                for (int ma = 0; ma < 2; ++ma)
                    ldmatrix_x4(afrag[kst][ma][0], afrag[kst][ma][1],
                                afrag[kst][ma][2], afrag[kst][ma][3],
                                abase + ma * 16 * ROWB + kst * 32);
            prevI = curI;
        }

        // ---- prefetch next tile (A-buf reusable: afrag lives in regs) ----
        if (nxtT < NPAIR) {
            if (nxtI != curI) {
                __syncthreads();   // all warps' afrag LDSM done before A overwrite
                cp_tile(sb + A_OFF, nxtI, tid);
            }
            cp_tile(sb + ((p ^ 1) ? B1_OFF : B0_OFF), nxtJ, tid);
        }
        CP_COMMIT();

        // ---- compute cur from B buffer p ----
        const bool diag = (curI == curJ);
        uint32_t colacc[8];
        #pragma unroll
        for (int na = 0; na < 8; ++na) colacc[na] = 0;
        uint32_t rlo[2] = {0, 0}, rhi[2] = {0, 0};

        uint32_t bbase = sb + (p ? B1_OFF : B0_OFF)
                       + (warp_n * 64 + (lane & 15)) * ROWB + (lane >> 4) * 16;

        #pragma unroll
        for (int pr = 0; pr < 4; ++pr) {
            float acc[2][2][4];
            #pragma unroll
            for (int ma = 0; ma < 2; ++ma)
                #pragma unroll
                for (int nl = 0; nl < 2; ++nl)
                    #pragma unroll
                    for (int q = 0; q < 4; ++q) acc[ma][nl][q] = 0.f;

            uint32_t bq[2][4];
            ldmatrix_x4(bq[0][0], bq[0][1], bq[0][2], bq[0][3],
                        bbase + pr * 16 * ROWB);
            #pragma unroll
            for (int kst = 0; kst < 8; ++kst) {
                int cb = kst & 1, nb = cb ^ 1;
                if (kst < 7)
                    ldmatrix_x4(bq[nb][0], bq[nb][1], bq[nb][2], bq[nb][3],
                                bbase + pr * 16 * ROWB + (kst + 1) * 32);
                mma_bf16(acc[0][0], afrag[kst][0], bq[cb][0], bq[cb][2]);
                mma_bf16(acc[0][1], afrag[kst][0], bq[cb][1], bq[cb][3]);
                mma_bf16(acc[1][0], afrag[kst][1], bq[cb][0], bq[cb][2]);
                mma_bf16(acc[1][1], afrag[kst][1], bq[cb][1], bq[cb][3]);
            }
            #pragma unroll
            for (int ma = 0; ma < 2; ++ma)
                #pragma unroll
                for (int nl = 0; nl < 2; ++nl) {
                    uint32_t e01 = ex2_f16x2(f16x2_pack(acc[ma][nl][0], acc[ma][nl][1]));
                    uint32_t e23 = ex2_f16x2(f16x2_pack(acc[ma][nl][2], acc[ma][nl][3]));
                    rlo[ma] = hadd2(rlo[ma], e01);
                    rhi[ma] = hadd2(rhi[ma], e23);
                    colacc[pr * 2 + nl] = hadd2(colacc[pr * 2 + nl], hadd2(e01, e23));
                }
        }

        // fold tile row partials into persistent f32 accumulators
        #pragma unroll
        for (int ma = 0; ma < 2; ++ma) {
            float2 glo = __half22float2(*(__half2*)&rlo[ma]);
            float2 ghi = __half22float2(*(__half2*)&rhi[ma]);
            rs[ma*2]     += glo.x + glo.y;
            rs[ma*2 + 1] += ghi.x + ghi.y;
        }

        // ---- colsum flush (per tile; symmetry) ----
        if (!diag) {
            #pragma unroll
            for (int na = 0; na < 8; ++na) {
                uint32_t v = colacc[na];
                v = hadd2(v, __shfl_xor_sync(0xffffffffu, v, 4));
                v = hadd2(v, __shfl_xor_sync(0xffffffffu, v, 8));
                v = hadd2(v, __shfl_xor_sync(0xffffffffu, v, 16));
                if (lane < 4) {
                    float2 cs = __half22float2(*(__half2*)&v);
                    int col = curJ * 128 + warp_n * 64 + na * 8 + lane * 2;
                    atomicAdd(&g_rowsum[col],     cs.x);
                    atomicAdd(&g_rowsum[col + 1], cs.y);
                }
            }
        }

        // ---- rotate ----
        curT = nxtT; curI = nxtI; curJ = nxtJ;
        p ^= 1;
    }

    // ---- final deferred row flush ----
    if (prevI >= 0) {
        #pragma unroll
        for (int i = 0; i < 4; ++i) {
            rs[i] += __shfl_xor_sync(0xffffffffu, rs[i], 1);
            rs[i] += __shfl_xor_sync(0xffffffffu, rs[i], 2);
        }
        if ((lane & 3) == 0) {
            int r8 = lane >> 2;
            #pragma unroll
            for (int i = 0; i < 4; ++i)
                atomicAdd(&g_rowsum[prevI * 128 + warp_m * 32 + i * 8 + r8], rs[i]);
        }
    }
}

// ============================================================
// Kernel C: loss = mean( log(rowsum - exp(2)) - 2*pos )
// ============================================================
__global__ void nt_loss_kernel(float* __restrict__ out) {
    __shared__ double sred[32];
    const int tid  = threadIdx.x;   // 1024
    const int lane = tid & 31;
    const int wid  = tid >> 5;

    double s = 0.0;
    for (int i = tid; i < TWON; i += 1024) {
        float denom = g_rowsum[i] - DIAG_EXP2;
        float term  = logf(denom) - 2.0f * g_pos[i & (N - 1)];
        s += (double)term;
    }
    #pragma unroll
    for (int o = 16; o; o >>= 1) s += __shfl_xor_sync(0xffffffffu, s, o);
    if (lane == 0) sred[wid] = s;
    __syncthreads();
    if (wid == 0) {
        double tt = sred[lane];
        #pragma unroll
        for (int o = 16; o; o >>= 1) tt += __shfl_xor_sync(0xffffffffu, tt, o);
        if (lane == 0) out[0] = (float)(tt / (double)TWON);
    }
}

// ============================================================
extern "C" void kernel_launch(void* const* d_in, const int* in_sizes, int n_in,
                              void* d_out, int out_size) {
    const float* h1 = (const float*)d_in[0];
    const float* h2 = (const float*)d_in[1];
    float* out = (float*)d_out;

    nt_norm_kernel<<<1024, 256>>>(h1, h2);

    cudaFuncSetAttribute(nt_gemm_sym,
                         cudaFuncAttributeMaxDynamicSharedMemorySize, SMEM_SZ);
    nt_gemm_sym<<<296, NT, SMEM_SZ>>>();

    nt_loss_kernel<<<1, 1024>>>(out);
}

// round 12
// speedup vs baseline: 1.3320x; 1.0711x over previous
#include <cuda_runtime.h>
#include <cuda_fp16.h>
#include <math.h>
#include <stdint.h>

#define N     8192
#define D     128
#define TWON  16384
#define NTILE 128
#define NPAIR 8256             // NTILE*(NTILE+1)/2
#define CHUNK 4

#define DIAG_EXP2  7.38905609893065f
#define SQRT_SCALE 1.6986436f  // sqrt(2/ln2): acc = log2(exp arg)

// -------- persistent device scratch --------
__device__ __half g_Hh[TWON * D];   // normalized rows, pre-scaled, fp16
__device__ float g_pos[N];
__device__ float g_rowsum[TWON];
__device__ int   g_ctr;

// ============================================================
// helpers
// ============================================================
__device__ __forceinline__ uint32_t smem_u32(const void* p) {
    uint32_t a;
    asm("{ .reg .u64 t; cvta.to.shared.u64 t, %1; cvt.u32.u64 %0, t; }" : "=r"(a) : "l"(p));
    return a;
}
__device__ __forceinline__ void cp_async16(uint32_t saddr, const void* gaddr) {
    asm volatile("cp.async.cg.shared.global [%0], [%1], 16;" :: "r"(saddr), "l"(gaddr) : "memory");
}
#define CP_COMMIT() asm volatile("cp.async.commit_group;" ::: "memory")
#define CP_WAIT0()  asm volatile("cp.async.wait_group 0;" ::: "memory")

__device__ __forceinline__ void ldmatrix_x4(uint32_t& r0, uint32_t& r1, uint32_t& r2,
                                            uint32_t& r3, uint32_t addr) {
    asm volatile("ldmatrix.sync.aligned.m8n8.x4.shared.b16 {%0,%1,%2,%3}, [%4];"
                 : "=r"(r0), "=r"(r1), "=r"(r2), "=r"(r3) : "r"(addr));
}
// fp16 in, fp16 accumulate: C regs are 2x f16x2
__device__ __forceinline__ void mma_f16(uint32_t* c, const uint32_t* a, uint32_t b0, uint32_t b1) {
    asm volatile("mma.sync.aligned.m16n8k16.row.col.f16.f16.f16.f16 "
                 "{%0,%1}, {%2,%3,%4,%5}, {%6,%7}, {%0,%1};"
                 : "+r"(c[0]), "+r"(c[1])
                 : "r"(a[0]), "r"(a[1]), "r"(a[2]), "r"(a[3]), "r"(b0), "r"(b1));
}
__device__ __forceinline__ uint32_t ex2_f16x2(uint32_t x) {
    uint32_t y;
    asm("ex2.approx.f16x2 %0, %1;" : "=r"(y) : "r"(x));
    return y;
}
__device__ __forceinline__ uint32_t hadd2(uint32_t a, uint32_t b) {
    uint32_t r;
    asm("add.rn.f16x2 %0, %1, %2;" : "=r"(r) : "r"(a), "r"(b));
    return r;
}
// t in [0, NPAIR) -> (I,J), I<=J, row-major over upper triangle
__device__ __forceinline__ void decode_pair(int t, int& I, int& J) {
    int r = NPAIR - t;
    float nf = (sqrtf(8.0f * (float)r + 1.0f) - 1.0f) * 0.5f;
    int n = (int)ceilf(nf);
    while (n * (n + 1) / 2 < r) n++;
    while (n >= 1 && (n - 1) * n / 2 >= r) n--;
    I = NTILE - n;
    int S = NPAIR - n * (n + 1) / 2;
    J = I + (t - S);
}

// ============================================================
// Kernel A: normalize + pre-scale to fp16; zero rowsum/ctr
// ============================================================
__global__ void nt_norm_kernel(const float* __restrict__ h1,
                               const float* __restrict__ h2) {
    int gid = blockIdx.x * blockDim.x + threadIdx.x;
    if (gid < TWON) g_rowsum[gid] = 0.0f;
    if (gid == 0)   g_ctr = 0;

    int warp = gid >> 5;
    int lane = threadIdx.x & 31;
    if (warp >= N) return;

    float4 a = ((const float4*)(h1 + (size_t)warp * D))[lane];
    float4 b = ((const float4*)(h2 + (size_t)warp * D))[lane];

    float sa = a.x*a.x + a.y*a.y + a.z*a.z + a.w*a.w;
    float sb = b.x*b.x + b.y*b.y + b.z*b.z + b.w*b.w;
    float sd = a.x*b.x + a.y*b.y + a.z*b.z + a.w*b.w;
    #pragma unroll
    for (int o = 16; o; o >>= 1) {
        sa += __shfl_xor_sync(0xffffffffu, sa, o);
        sb += __shfl_xor_sync(0xffffffffu, sb, o);
        sd += __shfl_xor_sync(0xffffffffu, sd, o);
    }
    float ra = 1.0f / fmaxf(sqrtf(sa), 1e-12f);
    float rb = 1.0f / fmaxf(sqrtf(sb), 1e-12f);
    if (lane == 0) g_pos[warp] = sd * ra * rb;

    float fa = ra * SQRT_SCALE, fb = rb * SQRT_SCALE;
    union { __half2 h2v[2]; uint2 u; } pa, pb;
    pa.h2v[0] = __floats2half2_rn(a.x*fa, a.y*fa);
    pa.h2v[1] = __floats2half2_rn(a.z*fa, a.w*fa);
    pb.h2v[0] = __floats2half2_rn(b.x*fb, b.y*fb);
    pb.h2v[1] = __floats2half2_rn(b.z*fb, b.w*fb);
    ((uint2*)(g_Hh + (size_t)warp * D))[lane]       = pa.u;
    ((uint2*)(g_Hh + (size_t)(warp + N) * D))[lane] = pb.u;
}

// ============================================================
// Kernel B: symmetric persistent GEMM — occ 2, fp16-accum HMMA.
//   smem = A buf + 2 B bufs = 104448B -> 2 CTAs/SM, grid 296.
// ============================================================
#define PADROW    136
#define ROWB      (PADROW * 2)           // 272B
#define T_BYTES   (128 * ROWB)           // 34816
#define A_OFF     0
#define B0_OFF    T_BYTES
#define B1_OFF    (2 * T_BYTES)
#define SMEM_SZ   (3 * T_BYTES)          // 104448
#define NT        256

__device__ __forceinline__ void cp_tile(uint32_t buf, int blk, int tid) {
    const __half* src = g_Hh + (size_t)blk * 128 * D;
    #pragma unroll
    for (int c = tid; c < 2048; c += NT) {
        int r = c >> 4, kc = c & 15;
        cp_async16(buf + r * ROWB + kc * 16, src + (size_t)r * D + kc * 8);
    }
}

__global__ void __launch_bounds__(NT, 2) nt_gemm_sym() {
    extern __shared__ char smem[];
    __shared__ int s_c;
    uint32_t sb = smem_u32(smem);
    const int tid    = threadIdx.x;
    const int lane   = tid & 31;
    const int wid    = tid >> 5;
    const int warp_m = wid & 3;      // rows warp_m*32
    const int warp_n = wid >> 2;     // cols warp_n*64

    // ---- first chunk + first tile load ----
    if (tid == 0) s_c = atomicAdd(&g_ctr, 1);
    __syncthreads();
    int cpos = s_c * CHUNK;
    int cend = cpos + CHUNK;
    if (cpos >= NPAIR) { cpos = NPAIR; cend = NPAIR; }

    int curT = (cpos < cend) ? cpos++ : NPAIR;
    int curI = 0, curJ = 0;
    if (curT < NPAIR) {
        decode_pair(curT, curI, curJ);
        cp_tile(sb + A_OFF, curI, tid);
        cp_tile(sb + B0_OFF, curJ, tid);
    }
    CP_COMMIT();

    int p = 0, prevI = -1;
    uint32_t afrag[8][2][4];
    float rs[4] = {0.f, 0.f, 0.f, 0.f};

    while (curT < NPAIR) {
        // ---- acquire next index; wait cur data; one block sync ----
        bool need = (cpos >= cend);
        if (need && tid == 0) s_c = atomicAdd(&g_ctr, 1);
        CP_WAIT0();
        __syncthreads();
        if (need) {
            cpos = s_c * CHUNK;
            if (cpos > NPAIR) cpos = NPAIR;
            cend = cpos + CHUNK;
            if (cend > NPAIR) cend = NPAIR;
        }
        int nxtT = (cpos < cend) ? cpos++ : NPAIR;
        int nxtI = 0, nxtJ = 0;
        if (nxtT < NPAIR) decode_pair(nxtT, nxtI, nxtJ);

        // ---- I changed: flush deferred row sums, (re)load A fragments ----
        if (curI != prevI) {
            if (prevI >= 0) {
                #pragma unroll
                for (int i = 0; i < 4; ++i) {
                    rs[i] += __shfl_xor_sync(0xffffffffu, rs[i], 1);
                    rs[i] += __shfl_xor_sync(0xffffffffu, rs[i], 2);
                }
                if ((lane & 3) == 0) {
                    int r8 = lane >> 2;
                    #pragma unroll
                    for (int i = 0; i < 4; ++i)
                        atomicAdd(&g_rowsum[prevI * 128 + warp_m * 32 + i * 8 + r8], rs[i]);
                }
                rs[0] = rs[1] = rs[2] = rs[3] = 0.f;
            }
            uint32_t abase = sb + A_OFF + (warp_m * 32 + (lane & 15)) * ROWB + (lane >> 4) * 16;
            #pragma unroll
            for (int kst = 0; kst < 8; ++kst)
                #pragma unroll
                for (int ma = 0; ma < 2; ++ma)
                    ldmatrix_x4(afrag[kst][ma][0], afrag[kst][ma][1],
                                afrag[kst][ma][2], afrag[kst][ma][3],
                                abase + ma * 16 * ROWB + kst * 32);
            prevI = curI;
        }

        // ---- prefetch next tile (A-buf reusable: afrag lives in regs) ----
        if (nxtT < NPAIR) {
            if (nxtI != curI) {
                __syncthreads();   // all warps' afrag LDSM done before A overwrite
                cp_tile(sb + A_OFF, nxtI, tid);
            }
            cp_tile(sb + ((p ^ 1) ? B1_OFF : B0_OFF), nxtJ, tid);
        }
        CP_COMMIT();

        // ---- compute cur from B buffer p ----
        const bool diag = (curI == curJ);
        uint32_t colacc[8];
        #pragma unroll
        for (int na = 0; na < 8; ++na) colacc[na] = 0;
        uint32_t rlo[2] = {0, 0}, rhi[2] = {0, 0};

        uint32_t bbase = sb + (p ? B1_OFF : B0_OFF)
                       + (warp_n * 64 + (lane & 15)) * ROWB + (lane >> 4) * 16;

        #pragma unroll
        for (int pr = 0; pr < 4; ++pr) {
            // f16 accumulators: [ma][nl] -> 2 regs (f16x2: row r / row r+8)
            uint32_t acc[2][2][2];
            #pragma unroll
            for (int ma = 0; ma < 2; ++ma)
                #pragma unroll
                for (int nl = 0; nl < 2; ++nl)
                    acc[ma][nl][0] = acc[ma][nl][1] = 0;

            uint32_t bq[2][4];
            ldmatrix_x4(bq[0][0], bq[0][1], bq[0][2], bq[0][3],
                        bbase + pr * 16 * ROWB);
            #pragma unroll
            for (int kst = 0; kst < 8; ++kst) {
                int cb = kst & 1, nb = cb ^ 1;
                if (kst < 7)
                    ldmatrix_x4(bq[nb][0], bq[nb][1], bq[nb][2], bq[nb][3],
                                bbase + pr * 16 * ROWB + (kst + 1) * 32);
                mma_f16(acc[0][0], afrag[kst][0], bq[cb][0], bq[cb][2]);
                mma_f16(acc[0][1], afrag[kst][0], bq[cb][1], bq[cb][3]);
                mma_f16(acc[1][0], afrag[kst][1], bq[cb][0], bq[cb][2]);
                mma_f16(acc[1][1], afrag[kst][1], bq[cb][1], bq[cb][3]);
            }
            // epilogue: exp2 directly on packed f16 accumulators
            #pragma unroll
            for (int ma = 0; ma < 2; ++ma)
                #pragma unroll
                for (int nl = 0; nl < 2; ++nl) {
                    uint32_t e01 = ex2_f16x2(acc[ma][nl][0]);   // cols c,c+1 of row r
                    uint32_t e23 = ex2_f16x2(acc[ma][nl][1]);   // cols c,c+1 of row r+8
                    rlo[ma] = hadd2(rlo[ma], e01);
                    rhi[ma] = hadd2(rhi[ma], e23);
                    colacc[pr * 2 + nl] = hadd2(colacc[pr * 2 + nl], hadd2(e01, e23));
                }
        }

        // fold tile row partials into persistent f32 accumulators
        #pragma unroll
        for (int ma = 0; ma < 2; ++ma) {
            float2 glo = __half22float2(*(__half2*)&rlo[ma]);
            float2 ghi = __half22float2(*(__half2*)&rhi[ma]);
            rs[ma*2]     += glo.x + glo.y;
            rs[ma*2 + 1] += ghi.x + ghi.y;
        }

        // ---- colsum flush (per tile; symmetry) ----
        if (!diag) {
            #pragma unroll
            for (int na = 0; na < 8; ++na) {
                uint32_t v = colacc[na];
                v = hadd2(v, __shfl_xor_sync(0xffffffffu, v, 4));
                v = hadd2(v, __shfl_xor_sync(0xffffffffu, v, 8));
                v = hadd2(v, __shfl_xor_sync(0xffffffffu, v, 16));
                if (lane < 4) {
                    float2 cs = __half22float2(*(__half2*)&v);
                    int col = curJ * 128 + warp_n * 64 + na * 8 + lane * 2;
                    atomicAdd(&g_rowsum[col],     cs.x);
                    atomicAdd(&g_rowsum[col + 1], cs.y);
                }
            }
        }

        // ---- rotate ----
        curT = nxtT; curI = nxtI; curJ = nxtJ;
        p ^= 1;
    }

    // ---- final deferred row flush ----
    if (prevI >= 0) {
        #pragma unroll
        for (int i = 0; i < 4; ++i) {
            rs[i] += __shfl_xor_sync(0xffffffffu, rs[i], 1);
            rs[i] += __shfl_xor_sync(0xffffffffu, rs[i], 2);
        }
        if ((lane & 3) == 0) {
            int r8 = lane >> 2;
            #pragma unroll
            for (int i = 0; i < 4; ++i)
                atomicAdd(&g_rowsum[prevI * 128 + warp_m * 32 + i * 8 + r8], rs[i]);
        }
    }
}

// ============================================================
// Kernel C: loss = mean( log(rowsum - exp(2)) - 2*pos )
// ============================================================
__global__ void nt_loss_kernel(float* __restrict__ out) {
    __shared__ double sred[32];
    const int tid  = threadIdx.x;   // 1024
    const int lane = tid & 31;
    const int wid  = tid >> 5;

    double s = 0.0;
    for (int i = tid; i < TWON; i += 1024) {
        float denom = g_rowsum[i] - DIAG_EXP2;
        float term  = logf(denom) - 2.0f * g_pos[i & (N - 1)];
        s += (double)term;
    }
    #pragma unroll
    for (int o = 16; o; o >>= 1) s += __shfl_xor_sync(0xffffffffu, s, o);
    if (lane == 0) sred[wid] = s;
    __syncthreads();
    if (wid == 0) {
        double tt = sred[lane];
        #pragma unroll
        for (int o = 16; o; o >>= 1) tt += __shfl_xor_sync(0xffffffffu, tt, o);
        if (lane == 0) out[0] = (float)(tt / (double)TWON);
    }
}

// ============================================================
extern "C" void kernel_launch(void* const* d_in, const int* in_sizes, int n_in,
                              void* d_out, int out_size) {
    const float* h1 = (const float*)d_in[0];
    const float* h2 = (const float*)d_in[1];
    float* out = (float*)d_out;

    nt_norm_kernel<<<1024, 256>>>(h1, h2);

    cudaFuncSetAttribute(nt_gemm_sym,
                         cudaFuncAttributeMaxDynamicSharedMemorySize, SMEM_SZ);
    nt_gemm_sym<<<296, NT, SMEM_SZ>>>();

    nt_loss_kernel<<<1, 1024>>>(out);
}